// round 3
// baseline (speedup 1.0000x reference)
#include <cuda_runtime.h>
#include <cstdint>

#define NUM_CLASSES 1000
#define D 512
#define N_MAX 131072
#define EPT 8

// ---------------- scratch (no allocations allowed) ----------------
__device__ int   g_counts[NUM_CLASSES];          // zero at load; re-zeroed by pairwise tail
__device__ int   g_offsets[NUM_CLASSES + 1];
__device__ int   g_cursor[NUM_CLASSES];
__device__ int   g_sorted[N_MAX];
__device__ float g_centers[NUM_CLASSES * D];
__device__ float g_sq[NUM_CLASSES];
__device__ int   g_minbits = 0x7F800000;         // +inf; re-armed by pairwise tail
__device__ int   g_done    = 0;

// per-block label dtype sniff: if labels are int32, int64-reinterpreted values
// are out of [0,1000) almost surely within the first 512 words.
__device__ __forceinline__ int block_is64(const void* labels) {
    __shared__ int s64;
    if (threadIdx.x == 0) s64 = 1;
    __syncthreads();
    int bad = 0;
    for (int i = threadIdx.x; i < 512; i += blockDim.x) {
        long long v = ((const long long*)labels)[i];
        if (v < 0 || v >= NUM_CLASSES) bad = 1;
    }
    if (bad) s64 = 0;
    __syncthreads();
    return s64;
}

__device__ __forceinline__ int load_label(const void* labels, int i, int is64) {
    if (is64) return (int)((const long long*)labels)[i];
    return ((const int*)labels)[i];
}

// K0: histogram, 8 labels per thread (batched atomics)
__global__ void __launch_bounds__(256) k_hist(const void* labels, int n) {
    int is64 = block_is64(labels);
    int base = (blockIdx.x * blockDim.x + threadIdx.x) * EPT;
#pragma unroll
    for (int u = 0; u < EPT; u++) {
        int i = base + u;
        if (i < n) atomicAdd(&g_counts[load_label(labels, i, is64)], 1);
    }
}

// K1: exclusive scan over 1000 counts (shfl warp-scan)
__global__ void k_scan(int n) {
    __shared__ int wsum[32];
    int t = threadIdx.x, lane = t & 31, warp = t >> 5;
    int v = (t < NUM_CLASSES) ? g_counts[t] : 0;
    int x = v;
#pragma unroll
    for (int off = 1; off < 32; off <<= 1) {
        int y = __shfl_up_sync(0xFFFFFFFF, x, off);
        if (lane >= off) x += y;
    }
    if (lane == 31) wsum[warp] = x;
    __syncthreads();
    if (t < 32) {
        int w = wsum[t];
#pragma unroll
        for (int off = 1; off < 32; off <<= 1) {
            int y = __shfl_up_sync(0xFFFFFFFF, w, off);
            if (lane >= off) w += y;
        }
        wsum[t] = w;
    }
    __syncthreads();
    int base = (warp > 0) ? wsum[warp - 1] : 0;
    int excl = base + x - v;
    if (t < NUM_CLASSES) { g_offsets[t] = excl; g_cursor[t] = excl; }
    if (t == 0) g_offsets[NUM_CLASSES] = n;
}

// K2: scatter row indices into class-sorted order, 8 per thread (MLP on atomics)
__global__ void __launch_bounds__(256) k_scatter(const void* labels, int n) {
    int is64 = block_is64(labels);
    int base = (blockIdx.x * blockDim.x + threadIdx.x) * EPT;
    int lab[EPT], pos[EPT];
#pragma unroll
    for (int u = 0; u < EPT; u++)
        lab[u] = (base + u < n) ? load_label(labels, base + u, is64) : -1;
#pragma unroll
    for (int u = 0; u < EPT; u++)
        if (lab[u] >= 0) pos[u] = atomicAdd(&g_cursor[lab[u]], 1);
#pragma unroll
    for (int u = 0; u < EPT; u++)
        if (lab[u] >= 0) g_sorted[pos[u]] = base + u;
}

// K3: per-class mean in registers; thread t owns columns 2t, 2t+1 (float2 loads).
__global__ void __launch_bounds__(256) k_classsum(const float* __restrict__ f) {
    int c = blockIdx.x;
    int t = threadIdx.x;
    int s = g_offsets[c], e = g_offsets[c + 1];
    int cnt = e - s;

    __shared__ int sidx[512];
    float ax[8], ay[8];
#pragma unroll
    for (int u = 0; u < 8; u++) { ax[u] = 0.f; ay[u] = 0.f; }

    for (int base = s; base < e; base += 512) {
        int m = e - base; if (m > 512) m = 512;
        __syncthreads();
        for (int i = t; i < m; i += 256) sidx[i] = g_sorted[base + i];
        __syncthreads();
        int r = 0;
        for (; r + 8 <= m; r += 8) {
#pragma unroll
            for (int u = 0; u < 8; u++) {
                float2 v = *(const float2*)&f[(size_t)sidx[r + u] * D + 2 * t];
                ax[u] += v.x; ay[u] += v.y;
            }
        }
        for (; r < m; r++) {
            float2 v = *(const float2*)&f[(size_t)sidx[r] * D + 2 * t];
            ax[0] += v.x; ay[0] += v.y;
        }
    }
    float sx = ((ax[0] + ax[1]) + (ax[2] + ax[3])) + ((ax[4] + ax[5]) + (ax[6] + ax[7]));
    float sy = ((ay[0] + ay[1]) + (ay[2] + ay[3])) + ((ay[4] + ay[5]) + (ay[6] + ay[7]));
    float denom = fmaxf((float)cnt, 1.0f);
    float cx = sx / denom, cy = sy / denom;
    g_centers[c * D + 2 * t]     = cx;
    g_centers[c * D + 2 * t + 1] = cy;

    // reduce sum(center^2) across block
    float v = cx * cx + cy * cy;
#pragma unroll
    for (int off = 16; off > 0; off >>= 1)
        v += __shfl_down_sync(0xFFFFFFFF, v, off);
    __shared__ float ws[8];
    int warp = t >> 5, lane = t & 31;
    if (lane == 0) ws[warp] = v;
    __syncthreads();
    if (t == 0) {
        float w = 0.f;
#pragma unroll
        for (int i = 0; i < 8; i++) w += ws[i];
        g_sq[c] = w;
    }
}

// K4: pairwise min via packed fma.rn.f32x2 (FFMA2). dis = sq[i]+sq[j]-2*dot
// (diagonal included, filtered by >0, same as reference). Upper-triangle tiles.
#define PT 64
#define KC 32
#define SA (2 * PT + 2)   // Adup row stride (floats), even -> 8B-aligned pairs
#define SB (PT + 2)       // Bs row stride (floats), even
#define GRID_PW 16

__device__ __forceinline__ void ffma2(unsigned long long& d,
                                      unsigned long long a,
                                      unsigned long long b) {
    asm("fma.rn.f32x2 %0, %1, %2, %0;" : "+l"(d) : "l"(a), "l"(b));
}

__global__ void __launch_bounds__(256) k_pairwise(float* __restrict__ out) {
    int bi = blockIdx.x, bj = blockIdx.y;
    int tid = threadIdx.x;

    __shared__ float Adup[KC][SA];   // Adup[k][2m] = Adup[k][2m+1] = A[m][k]
    __shared__ float Bs[KC][SB];     // Bs[k][j] = B[j][k]

    if (bj >= bi) {
        int tx = tid & 15;   // j micro index (4 cols)
        int ty = tid >> 4;   // i micro index (4 rows)

        unsigned long long acc2[4][2];
#pragma unroll
        for (int r = 0; r < 4; r++) { acc2[r][0] = 0ull; acc2[r][1] = 0ull; }

        int rowb = tid >> 3;        // 0..31
        int kk   = (tid & 7) * 4;   // 0..28

        for (int k0 = 0; k0 < D; k0 += KC) {
            __syncthreads();
#pragma unroll
            for (int rr = 0; rr < 2; rr++) {
                int row = rowb + rr * 32;
                int gi = bi * PT + row;
                int gj = bj * PT + row;
                float4 av = (gi < NUM_CLASSES)
                    ? *(const float4*)&g_centers[gi * D + k0 + kk]
                    : make_float4(0.f, 0.f, 0.f, 0.f);
                float4 bv = (gj < NUM_CLASSES)
                    ? *(const float4*)&g_centers[gj * D + k0 + kk]
                    : make_float4(0.f, 0.f, 0.f, 0.f);
                *(float2*)&Adup[kk + 0][2 * row] = make_float2(av.x, av.x);
                *(float2*)&Adup[kk + 1][2 * row] = make_float2(av.y, av.y);
                *(float2*)&Adup[kk + 2][2 * row] = make_float2(av.z, av.z);
                *(float2*)&Adup[kk + 3][2 * row] = make_float2(av.w, av.w);
                Bs[kk + 0][row] = bv.x;
                Bs[kk + 1][row] = bv.y;
                Bs[kk + 2][row] = bv.z;
                Bs[kk + 3][row] = bv.w;
            }
            __syncthreads();
#pragma unroll 4
            for (int k = 0; k < KC; k++) {
                unsigned long long b01 = *(const unsigned long long*)&Bs[k][4 * tx];
                unsigned long long b23 = *(const unsigned long long*)&Bs[k][4 * tx + 2];
#pragma unroll
                for (int r = 0; r < 4; r++) {
                    unsigned long long ar =
                        *(const unsigned long long*)&Adup[k][8 * ty + 2 * r];
                    ffma2(acc2[r][0], ar, b01);
                    ffma2(acc2[r][1], ar, b23);
                }
            }
        }

        float lmin = __int_as_float(0x7F800000);
#pragma unroll
        for (int r = 0; r < 4; r++) {
            int gi = bi * PT + ty * 4 + r;
            if (gi >= NUM_CLASSES) continue;
            float sqi = g_sq[gi];
#pragma unroll
            for (int p = 0; p < 2; p++) {
                unsigned long long u = acc2[r][p];
                float d0 = __int_as_float((int)(unsigned)(u & 0xFFFFFFFFull));
                float d1 = __int_as_float((int)(unsigned)(u >> 32));
                int gj0 = bj * PT + tx * 4 + 2 * p;
                if (gj0 < NUM_CLASSES) {
                    float dis = sqi + g_sq[gj0] - 2.0f * d0;
                    if (dis > 0.0f) lmin = fminf(lmin, dis);
                }
                if (gj0 + 1 < NUM_CLASSES) {
                    float dis = sqi + g_sq[gj0 + 1] - 2.0f * d1;
                    if (dis > 0.0f) lmin = fminf(lmin, dis);
                }
            }
        }
#pragma unroll
        for (int off = 16; off > 0; off >>= 1)
            lmin = fminf(lmin, __shfl_down_sync(0xFFFFFFFF, lmin, off));
        if ((tid & 31) == 0 && lmin < __int_as_float(0x7F800000))
            atomicMin(&g_minbits, __float_as_int(lmin));
    }

    // tail: final block writes output and resets state for the next replay
    __shared__ int s_last;
    if (tid == 0) {
        __threadfence();
        int d = atomicAdd(&g_done, 1);
        s_last = (d == GRID_PW * GRID_PW - 1) ? 1 : 0;
    }
    __syncthreads();
    if (s_last) {
        for (int i = tid; i < NUM_CLASSES; i += 256) g_counts[i] = 0;
        if (tid == 0) {
            float dmin = __int_as_float(g_minbits);
            out[0] = fmaxf(1.0f - dmin, 0.0f);   // MARGIN_INTER=1, BETA=1
            g_minbits = 0x7F800000;
            g_done = 0;
        }
    }
}

extern "C" void kernel_launch(void* const* d_in, const int* in_sizes, int n_in,
                              void* d_out, int out_size) {
    const float* features = (const float*)d_in[0];
    const void*  labels   = d_in[1];
    int n = in_sizes[1];
    float* out = (float*)d_out;

    int nb = (n + 256 * EPT - 1) / (256 * EPT);
    k_hist<<<nb, 256>>>(labels, n);
    k_scan<<<1, 1024>>>(n);
    k_scatter<<<nb, 256>>>(labels, n);
    k_classsum<<<NUM_CLASSES, 256>>>(features);
    dim3 pg(GRID_PW, GRID_PW);
    k_pairwise<<<pg, 256>>>(out);
}

// round 4
// speedup vs baseline: 1.0901x; 1.0901x over previous
#include <cuda_runtime.h>
#include <cstdint>

#define NUM_CLASSES 1000
#define D 512
#define N_MAX 131072
#define EPT 8

// ---------------- scratch (no allocations allowed) ----------------
__device__ int   g_counts[NUM_CLASSES];          // zero at load; re-zeroed by pairwise tail
__device__ int   g_offsets[NUM_CLASSES + 1];
__device__ int   g_cursor[NUM_CLASSES];
__device__ int   g_sorted[N_MAX];
__device__ float g_centers[NUM_CLASSES * D];
__device__ float g_sq[NUM_CLASSES];
__device__ int   g_minbits = 0x7F800000;         // +inf; re-armed by pairwise tail
__device__ int   g_done    = 0;

// per-block label dtype sniff: if labels are int32, int64-reinterpreted values
// are out of [0,1000) almost surely within the first 512 words.
__device__ __forceinline__ int block_is64(const void* labels) {
    __shared__ int s64;
    if (threadIdx.x == 0) s64 = 1;
    __syncthreads();
    int bad = 0;
    for (int i = threadIdx.x; i < 512; i += blockDim.x) {
        long long v = ((const long long*)labels)[i];
        if (v < 0 || v >= NUM_CLASSES) bad = 1;
    }
    if (bad) s64 = 0;
    __syncthreads();
    return s64;
}

__device__ __forceinline__ int load_label(const void* labels, int i, int is64) {
    if (is64) return (int)((const long long*)labels)[i];
    return ((const int*)labels)[i];
}

// K0: histogram, 8 labels per thread (batched atomics)
__global__ void __launch_bounds__(256) k_hist(const void* labels, int n) {
    int is64 = block_is64(labels);
    int base = (blockIdx.x * blockDim.x + threadIdx.x) * EPT;
#pragma unroll
    for (int u = 0; u < EPT; u++) {
        int i = base + u;
        if (i < n) atomicAdd(&g_counts[load_label(labels, i, is64)], 1);
    }
}

// K1: exclusive scan over 1000 counts (shfl warp-scan)
__global__ void k_scan(int n) {
    __shared__ int wsum[32];
    int t = threadIdx.x, lane = t & 31, warp = t >> 5;
    int v = (t < NUM_CLASSES) ? g_counts[t] : 0;
    int x = v;
#pragma unroll
    for (int off = 1; off < 32; off <<= 1) {
        int y = __shfl_up_sync(0xFFFFFFFF, x, off);
        if (lane >= off) x += y;
    }
    if (lane == 31) wsum[warp] = x;
    __syncthreads();
    if (t < 32) {
        int w = wsum[t];
#pragma unroll
        for (int off = 1; off < 32; off <<= 1) {
            int y = __shfl_up_sync(0xFFFFFFFF, w, off);
            if (lane >= off) w += y;
        }
        wsum[t] = w;
    }
    __syncthreads();
    int base = (warp > 0) ? wsum[warp - 1] : 0;
    int excl = base + x - v;
    if (t < NUM_CLASSES) { g_offsets[t] = excl; g_cursor[t] = excl; }
    if (t == 0) g_offsets[NUM_CLASSES] = n;
}

// K2: scatter row indices into class-sorted order, 8 per thread (MLP on atomics)
__global__ void __launch_bounds__(256) k_scatter(const void* labels, int n) {
    int is64 = block_is64(labels);
    int base = (blockIdx.x * blockDim.x + threadIdx.x) * EPT;
    int lab[EPT], pos[EPT];
#pragma unroll
    for (int u = 0; u < EPT; u++)
        lab[u] = (base + u < n) ? load_label(labels, base + u, is64) : -1;
#pragma unroll
    for (int u = 0; u < EPT; u++)
        if (lab[u] >= 0) pos[u] = atomicAdd(&g_cursor[lab[u]], 1);
#pragma unroll
    for (int u = 0; u < EPT; u++)
        if (lab[u] >= 0) g_sorted[pos[u]] = base + u;
}

// K3: per-class mean; 128 threads, thread t owns columns 4t..4t+3 (LDG.128),
// 8 rows unrolled -> 8 outstanding 16B loads per thread.
__global__ void __launch_bounds__(128) k_classsum(const float* __restrict__ f) {
    int c = blockIdx.x;
    int t = threadIdx.x;
    int s = g_offsets[c], e = g_offsets[c + 1];
    int cnt = e - s;

    __shared__ int sidx[256];
    float ax[8], ay[8], az[8], aw[8];
#pragma unroll
    for (int u = 0; u < 8; u++) { ax[u] = 0.f; ay[u] = 0.f; az[u] = 0.f; aw[u] = 0.f; }

    int col = 4 * t;
    for (int base = s; base < e; base += 256) {
        int m = e - base; if (m > 256) m = 256;
        __syncthreads();
        for (int i = t; i < m; i += 128) sidx[i] = g_sorted[base + i];
        __syncthreads();
        int r = 0;
        for (; r + 8 <= m; r += 8) {
#pragma unroll
            for (int u = 0; u < 8; u++) {
                float4 v = *(const float4*)&f[(size_t)sidx[r + u] * D + col];
                ax[u] += v.x; ay[u] += v.y; az[u] += v.z; aw[u] += v.w;
            }
        }
        for (; r < m; r++) {
            float4 v = *(const float4*)&f[(size_t)sidx[r] * D + col];
            ax[0] += v.x; ay[0] += v.y; az[0] += v.z; aw[0] += v.w;
        }
    }
    float sx = ((ax[0] + ax[1]) + (ax[2] + ax[3])) + ((ax[4] + ax[5]) + (ax[6] + ax[7]));
    float sy = ((ay[0] + ay[1]) + (ay[2] + ay[3])) + ((ay[4] + ay[5]) + (ay[6] + ay[7]));
    float sz = ((az[0] + az[1]) + (az[2] + az[3])) + ((az[4] + az[5]) + (az[6] + az[7]));
    float sw = ((aw[0] + aw[1]) + (aw[2] + aw[3])) + ((aw[4] + aw[5]) + (aw[6] + aw[7]));
    float denom = fmaxf((float)cnt, 1.0f);
    float4 cen = make_float4(sx / denom, sy / denom, sz / denom, sw / denom);
    *(float4*)&g_centers[c * D + col] = cen;

    // reduce sum(center^2) across block (4 warps)
    float v = cen.x * cen.x + cen.y * cen.y + cen.z * cen.z + cen.w * cen.w;
#pragma unroll
    for (int off = 16; off > 0; off >>= 1)
        v += __shfl_down_sync(0xFFFFFFFF, v, off);
    __shared__ float ws[4];
    int warp = t >> 5, lane = t & 31;
    if (lane == 0) ws[warp] = v;
    __syncthreads();
    if (t == 0) g_sq[c] = (ws[0] + ws[1]) + (ws[2] + ws[3]);
}

// K4: pairwise min over upper-triangle tiles (R1 layout — empirically best).
// dis = sq[i]+sq[j]-2*dot (diagonal included, filtered by >0, same as reference).
#define PT 64
#define KC 64
#define GRID_PW 16
__global__ void __launch_bounds__(256) k_pairwise(float* __restrict__ out) {
    int bi = blockIdx.x, bj = blockIdx.y;
    int tid = threadIdx.x;

    __shared__ float As[PT][KC + 1];
    __shared__ float Bs[PT][KC + 1];

    if (bj >= bi) {
        int tx = tid & 15;   // j micro index
        int ty = tid >> 4;   // i micro index

        float acc[4][4];
#pragma unroll
        for (int r = 0; r < 4; r++)
#pragma unroll
            for (int s2 = 0; s2 < 4; s2++) acc[r][s2] = 0.f;

        int rowb = tid >> 4;        // 0..15
        int kk   = (tid & 15) * 4;  // 0..60

        for (int k0 = 0; k0 < D; k0 += KC) {
            __syncthreads();
#pragma unroll
            for (int rr = 0; rr < 4; rr++) {
                int row = rowb + rr * 16;
                int gi = bi * PT + row;
                int gj = bj * PT + row;
                float4 av = (gi < NUM_CLASSES)
                    ? *(const float4*)&g_centers[gi * D + k0 + kk]
                    : make_float4(0.f, 0.f, 0.f, 0.f);
                float4 bv = (gj < NUM_CLASSES)
                    ? *(const float4*)&g_centers[gj * D + k0 + kk]
                    : make_float4(0.f, 0.f, 0.f, 0.f);
                As[row][kk] = av.x; As[row][kk + 1] = av.y; As[row][kk + 2] = av.z; As[row][kk + 3] = av.w;
                Bs[row][kk] = bv.x; Bs[row][kk + 1] = bv.y; Bs[row][kk + 2] = bv.z; Bs[row][kk + 3] = bv.w;
            }
            __syncthreads();
#pragma unroll
            for (int k = 0; k < KC; k++) {
                float a0 = As[ty * 4 + 0][k];
                float a1 = As[ty * 4 + 1][k];
                float a2 = As[ty * 4 + 2][k];
                float a3 = As[ty * 4 + 3][k];
                float b0 = Bs[tx * 4 + 0][k];
                float b1 = Bs[tx * 4 + 1][k];
                float b2 = Bs[tx * 4 + 2][k];
                float b3 = Bs[tx * 4 + 3][k];
                acc[0][0] += a0 * b0; acc[0][1] += a0 * b1; acc[0][2] += a0 * b2; acc[0][3] += a0 * b3;
                acc[1][0] += a1 * b0; acc[1][1] += a1 * b1; acc[1][2] += a1 * b2; acc[1][3] += a1 * b3;
                acc[2][0] += a2 * b0; acc[2][1] += a2 * b1; acc[2][2] += a2 * b2; acc[2][3] += a2 * b3;
                acc[3][0] += a3 * b0; acc[3][1] += a3 * b1; acc[3][2] += a3 * b2; acc[3][3] += a3 * b3;
            }
        }

        float lmin = __int_as_float(0x7F800000);
#pragma unroll
        for (int r = 0; r < 4; r++) {
            int gi = bi * PT + ty * 4 + r;
            if (gi >= NUM_CLASSES) continue;
            float sqi = g_sq[gi];
#pragma unroll
            for (int s2 = 0; s2 < 4; s2++) {
                int gj = bj * PT + tx * 4 + s2;
                if (gj >= NUM_CLASSES) continue;
                float dis = sqi + g_sq[gj] - 2.0f * acc[r][s2];
                if (dis > 0.0f) lmin = fminf(lmin, dis);
            }
        }
#pragma unroll
        for (int off = 16; off > 0; off >>= 1)
            lmin = fminf(lmin, __shfl_down_sync(0xFFFFFFFF, lmin, off));
        if ((tid & 31) == 0 && lmin < __int_as_float(0x7F800000))
            atomicMin(&g_minbits, __float_as_int(lmin));
    }

    // tail: final block writes output and resets state for the next replay
    __shared__ int s_last;
    if (tid == 0) {
        __threadfence();
        int d = atomicAdd(&g_done, 1);
        s_last = (d == GRID_PW * GRID_PW - 1) ? 1 : 0;
    }
    __syncthreads();
    if (s_last) {
        for (int i = tid; i < NUM_CLASSES; i += 256) g_counts[i] = 0;
        if (tid == 0) {
            float dmin = __int_as_float(g_minbits);
            out[0] = fmaxf(1.0f - dmin, 0.0f);   // MARGIN_INTER=1, BETA=1
            g_minbits = 0x7F800000;
            g_done = 0;
        }
    }
}

extern "C" void kernel_launch(void* const* d_in, const int* in_sizes, int n_in,
                              void* d_out, int out_size) {
    const float* features = (const float*)d_in[0];
    const void*  labels   = d_in[1];
    int n = in_sizes[1];
    float* out = (float*)d_out;

    int nb = (n + 256 * EPT - 1) / (256 * EPT);
    k_hist<<<nb, 256>>>(labels, n);
    k_scan<<<1, 1024>>>(n);
    k_scatter<<<nb, 256>>>(labels, n);
    k_classsum<<<NUM_CLASSES, 128>>>(features);
    dim3 pg(GRID_PW, GRID_PW);
    k_pairwise<<<pg, 256>>>(out);
}